// round 13
// baseline (speedup 1.0000x reference)
#include <cuda_runtime.h>
#include <cuda_fp16.h>
#include <cstdint>
#include <cstddef>

// Problem dims (fixed by the dataset)
#define TOKENS 8192
#define HIDDEN 2048
#define INTER  5632

// ---------------------------------------------------------------------------
// Scratch (device globals; no allocation allowed in kernel_launch)
// ---------------------------------------------------------------------------
__device__ __half g_wg[(size_t)HIDDEN * INTER];   // gate weight [H, I] fp16
__device__ __half g_wu[(size_t)HIDDEN * INTER];   // up weight   [H, I] fp16
__device__ __half g_wd[(size_t)INTER * HIDDEN];   // down weight [I, H] fp16
__device__ __half g_xh[(size_t)TOKENS * HIDDEN];  // x in fp16
__device__ __half g_h [(size_t)TOKENS * INTER];   // silu(xWg)*(xWu) in fp16

// ---------------------------------------------------------------------------
// Helpers
// ---------------------------------------------------------------------------
__device__ __forceinline__ void cp_async16(void* smem_dst, const void* gsrc) {
    uint32_t s = (uint32_t)__cvta_generic_to_shared(smem_dst);
    asm volatile("cp.async.cg.shared.global [%0], [%1], 16;\n" :: "r"(s), "l"(gsrc));
}
__device__ __forceinline__ void cp_commit() {
    asm volatile("cp.async.commit_group;\n");
}

__device__ __forceinline__ void ldmA(uint32_t r[4], uint32_t addr) {
    asm volatile("ldmatrix.sync.aligned.m8n8.x4.shared.b16 {%0,%1,%2,%3}, [%4];"
                 : "=r"(r[0]), "=r"(r[1]), "=r"(r[2]), "=r"(r[3]) : "r"(addr));
}
// x4 trans: returns {k0-7/n0-7, k8-15/n0-7, k0-7/n8-15, k8-15/n8-15}
__device__ __forceinline__ void ldmB4(uint32_t r[4], uint32_t addr) {
    asm volatile("ldmatrix.sync.aligned.m8n8.x4.trans.shared.b16 {%0,%1,%2,%3}, [%4];"
                 : "=r"(r[0]), "=r"(r[1]), "=r"(r[2]), "=r"(r[3]) : "r"(addr));
}

__device__ __forceinline__ void mma_f16(float c[4], const uint32_t a[4], const uint32_t* b) {
    asm volatile(
        "mma.sync.aligned.m16n8k16.row.col.f32.f16.f16.f32 "
        "{%0,%1,%2,%3}, {%4,%5,%6,%7}, {%8,%9}, {%0,%1,%2,%3};\n"
        : "+f"(c[0]), "+f"(c[1]), "+f"(c[2]), "+f"(c[3])
        : "r"(a[0]), "r"(a[1]), "r"(a[2]), "r"(a[3]),
          "r"(b[0]), "r"(b[1]));
}

__device__ __forceinline__ float silu(float v) {
    return v / (1.0f + __expf(-v));
}

// ---------------------------------------------------------------------------
// GPTQ int4 dequant -> fp16 [K, N] row-major
// ---------------------------------------------------------------------------
__global__ void dequant_kernel(const int* __restrict__ qw,
                               const int* __restrict__ qz,
                               const float* __restrict__ sc,
                               __half* __restrict__ w,
                               int in_dim, int out) {
    int o = blockIdx.x * blockDim.x + threadIdx.x;
    int kp = blockIdx.y;
    if (o >= out) return;
    int grp = kp >> 4;
    unsigned q = (unsigned)qw[(size_t)kp * out + o];
    unsigned zw = (unsigned)qz[(size_t)grp * (out >> 3) + (o >> 3)];
    int z = (int)((zw >> ((o & 7) * 4)) & 0xF) + 1;
    float s = sc[(size_t)grp * out + o];
#pragma unroll
    for (int j = 0; j < 8; j++) {
        int qv = (int)((q >> (4 * j)) & 0xF);
        w[(size_t)(kp * 8 + j) * out + o] = __float2half_rn((float)(qv - z) * s);
    }
}

// Convert x to fp16 (8 floats / thread)
__global__ void x_to_half_kernel(const float* __restrict__ x, __half* __restrict__ y, int n8) {
    int i = blockIdx.x * blockDim.x + threadIdx.x;
    if (i >= n8) return;
    float4 v0 = reinterpret_cast<const float4*>(x)[2 * i];
    float4 v1 = reinterpret_cast<const float4*>(x)[2 * i + 1];
    __half2 h[4];
    h[0] = __floats2half2_rn(v0.x, v0.y);
    h[1] = __floats2half2_rn(v0.z, v0.w);
    h[2] = __floats2half2_rn(v1.x, v1.y);
    h[3] = __floats2half2_rn(v1.z, v1.w);
    reinterpret_cast<uint4*>(y)[i] = *reinterpret_cast<uint4*>(h);
}

// ---------------------------------------------------------------------------
// Fused gate+up GEMM: h = fp16( silu(A@Bg) * (A@Bu) ), A[M,K], B*[K,N]
// CTA tile 128x128 (both matrices), BK=64, 4 stages, 256 threads,
// 8 warps 2(M)x4(N), warp tile 64x32 per matrix.
// Early dist-2 prefetch, ONE __syncthreads per ktile.  (R12 config — measured
// tensor 62.5%, 224 regs, no spill.)
// ---------------------------------------------------------------------------
constexpr int FBM = 128, FBN = 128, FBK = 64, FSTAGES = 4;
constexpr int FAST = 72;                 // halves per A row (144B); CF for ldmA
constexpr int FBST = 136;                // halves per B row (272B); CF for ldmB4
constexpr int FA_STAGE = FBM * FAST;     // 9216 halves
constexpr int FB_STAGE = FBK * FBST;     // 8704 halves
constexpr size_t FSMEM_BYTES = (size_t)FSTAGES * (FA_STAGE + 2 * FB_STAGE) * 2; // 212,992

__global__ void __launch_bounds__(256, 1)
fused_gateup_kernel(const __half* __restrict__ A,
                    const __half* __restrict__ Bg,
                    const __half* __restrict__ Bu,
                    __half* __restrict__ H, int M, int N, int K) {
    extern __shared__ __half smem[];
    __half* As  = smem;
    __half* Bgs = smem + FSTAGES * FA_STAGE;
    __half* Bus = Bgs + FSTAGES * FB_STAGE;
    const uint32_t As_u  = (uint32_t)__cvta_generic_to_shared(As);
    const uint32_t Bgs_u = (uint32_t)__cvta_generic_to_shared(Bgs);
    const uint32_t Bus_u = (uint32_t)__cvta_generic_to_shared(Bus);

    const int tid  = threadIdx.x;
    const int lane = tid & 31;
    const int wid  = tid >> 5;
    const int warpM = wid & 1;     // 0..1
    const int warpN = wid >> 1;    // 0..3
    const int bm = blockIdx.y * FBM;
    const int bn = blockIdx.x * FBN;

    // cp.async mapping (16B chunks):
    // A: 128 rows x 8 chunks -> 4/thread. B each: 64 rows x 16 chunks -> 4/thread.
    const int af8 = tid & 7;       // chunk in A row
    const int ar0 = tid >> 3;      // 0..31, rows +{0,32,64,96}
    const int bf8 = tid & 15;      // chunk in B row
    const int br0 = tid >> 4;      // 0..15, rows +{0,16,32,48}

    auto load_stage = [&](int st, int k0) {
        __half* as = As + st * FA_STAGE;
        __half* bgs = Bgs + st * FB_STAGE;
        __half* bus = Bus + st * FB_STAGE;
#pragma unroll
        for (int i = 0; i < 4; i++) {
            int r = ar0 + i * 32;
            cp_async16(as + r * FAST + af8 * 8,
                       A + (size_t)(bm + r) * K + k0 + af8 * 8);
        }
#pragma unroll
        for (int i = 0; i < 4; i++) {
            int r = br0 + i * 16;
            cp_async16(bgs + r * FBST + bf8 * 8,
                       Bg + (size_t)(k0 + r) * N + bn + bf8 * 8);
            cp_async16(bus + r * FBST + bf8 * 8,
                       Bu + (size_t)(k0 + r) * N + bn + bf8 * 8);
        }
        cp_commit();
    };

    float accg[4][4][4], accu[4][4][4];
#pragma unroll
    for (int mf = 0; mf < 4; mf++)
#pragma unroll
        for (int nf = 0; nf < 4; nf++)
#pragma unroll
            for (int i = 0; i < 4; i++) { accg[mf][nf][i] = 0.0f; accu[mf][nf][i] = 0.0f; }

    const int kTiles = K / FBK;
    load_stage(0, 0);
    load_stage(1, FBK);

    // Fragment addressing
    const int a_row = warpM * 64 + (lane & 15);
    const int a_k8  = (lane >> 4) * 8;
    const int b_row = (lane & 7) | (((lane >> 3) & 1) << 3);   // k offset 0..15
    const int b_col = warpN * 32 + ((lane >> 4) & 1) * 8;      // + q*16

    for (int kt = 0; kt < kTiles; ++kt) {
        if (kt + 2 < kTiles) {
            load_stage((kt + 2) % FSTAGES, (kt + 2) * FBK);
            asm volatile("cp.async.wait_group 2;\n");
        } else {
            asm volatile("cp.async.wait_group 0;\n");
        }
        __syncthreads();   // stage kt ready; writer is 2 ahead, laggard reader 1 behind (mod 4 distinct)

        const int cur = kt % FSTAGES;
        const uint32_t as_base = As_u + (uint32_t)(cur * FA_STAGE) * 2;
        const uint32_t bg_base = Bgs_u + (uint32_t)(cur * FB_STAGE) * 2;
        const uint32_t bu_base = Bus_u + (uint32_t)(cur * FB_STAGE) * 2;

#pragma unroll
        for (int kk = 0; kk < FBK; kk += 16) {
            uint32_t a[4][4];
            uint32_t bg[2][4];
            uint32_t bu[2][4];
#pragma unroll
            for (int mf = 0; mf < 4; mf++) {
                uint32_t addr = as_base +
                    ((uint32_t)(a_row + mf * 16) * FAST + kk + a_k8) * 2;
                ldmA(a[mf], addr);
            }
#pragma unroll
            for (int q = 0; q < 2; q++) {
                uint32_t off = ((uint32_t)(kk + b_row) * FBST + b_col + q * 16) * 2;
                ldmB4(bg[q], bg_base + off);
                ldmB4(bu[q], bu_base + off);
            }
#pragma unroll
            for (int mf = 0; mf < 4; mf++)
#pragma unroll
                for (int nf = 0; nf < 4; nf++) {
                    mma_f16(accg[mf][nf], a[mf], &bg[nf >> 1][(nf & 1) * 2]);
                    mma_f16(accu[mf][nf], a[mf], &bu[nf >> 1][(nf & 1) * 2]);
                }
        }
    }

    // Epilogue: h = fp16(silu(g)*u)
#pragma unroll
    for (int mf = 0; mf < 4; mf++) {
        int r0 = bm + warpM * 64 + mf * 16 + (lane >> 2);
#pragma unroll
        for (int nf = 0; nf < 4; nf++) {
            int c0 = bn + warpN * 32 + nf * 8 + (lane & 3) * 2;
            float* g = accg[mf][nf];
            float* u = accu[mf][nf];
            *reinterpret_cast<__half2*>(H + (size_t)r0 * N + c0) =
                __floats2half2_rn(silu(g[0]) * u[0], silu(g[1]) * u[1]);
            *reinterpret_cast<__half2*>(H + (size_t)(r0 + 8) * N + c0) =
                __floats2half2_rn(silu(g[2]) * u[2], silu(g[3]) * u[3]);
        }
    }
}

// ---------------------------------------------------------------------------
// fp16 GEMM (down proj): C[M,N] = A[M,K] @ B[K,N], fp32 out
// CTA tile 128x256, BK=32 (keeps regs ~210, no spill), 4 stages, 256 threads,
// warps 2x4, warp 64x64. Early dist-2 prefetch, ONE __syncthreads per ktile.
// ---------------------------------------------------------------------------
constexpr int BM = 128, BN = 256, BK = 32, STAGES = 4;
constexpr int AST = 40;               // halves per A row
constexpr int BST = 264;              // halves per B row
constexpr int A_STAGE = BM * AST;     // 5120 halves
constexpr int B_STAGE = BK * BST;     // 8448 halves
constexpr size_t SMEM_BYTES = (size_t)STAGES * (A_STAGE + B_STAGE) * 2;  // 108,544

__global__ void __launch_bounds__(256, 1)
gemm_f16_kernel(const __half* __restrict__ A, const __half* __restrict__ B,
                float* __restrict__ C, int M, int N, int K) {
    extern __shared__ __half smem[];
    __half* As = smem;
    __half* Bs = smem + STAGES * A_STAGE;
    const uint32_t As_u = (uint32_t)__cvta_generic_to_shared(As);
    const uint32_t Bs_u = (uint32_t)__cvta_generic_to_shared(Bs);

    const int tid  = threadIdx.x;
    const int lane = tid & 31;
    const int wid  = tid >> 5;
    const int warpM = wid & 1;
    const int warpN = wid >> 1;
    const int bm = blockIdx.y * BM;
    const int bn = blockIdx.x * BN;

    // cp.async mapping: A 128 rows x 4 chunks -> 2/thread; B 32 rows x 32 chunks -> 4/thread
    const int af8 = tid & 3;
    const int ar0 = tid >> 2;      // 0..63, rows +{0,64}
    const int bf8 = tid & 31;
    const int br0 = tid >> 5;      // 0..7, rows +{0,8,16,24}

    auto load_stage = [&](int st, int k0) {
        __half* as = As + st * A_STAGE;
        __half* bs = Bs + st * B_STAGE;
#pragma unroll
        for (int i = 0; i < 2; i++) {
            int r = ar0 + i * 64;
            cp_async16(as + r * AST + af8 * 8,
                       A + (size_t)(bm + r) * K + k0 + af8 * 8);
        }
#pragma unroll
        for (int i = 0; i < 4; i++) {
            int r = br0 + i * 8;
            cp_async16(bs + r * BST + bf8 * 8,
                       B + (size_t)(k0 + r) * N + bn + bf8 * 8);
        }
        cp_commit();
    };

    float acc[4][8][4];
#pragma unroll
    for (int mf = 0; mf < 4; mf++)
#pragma unroll
        for (int nf = 0; nf < 8; nf++)
#pragma unroll
            for (int i = 0; i < 4; i++) acc[mf][nf][i] = 0.0f;

    const int kTiles = K / BK;
    load_stage(0, 0);
    load_stage(1, BK);

    const int a_row = warpM * 64 + (lane & 15);
    const int a_k8  = (lane >> 4) * 8;
    const int b_row = (lane & 7) | (((lane >> 3) & 1) << 3);
    const int b_col = warpN * 64 + ((lane >> 4) & 1) * 8;   // + q*16

    for (int kt = 0; kt < kTiles; ++kt) {
        if (kt + 2 < kTiles) {
            load_stage((kt + 2) % STAGES, (kt + 2) * BK);
            asm volatile("cp.async.wait_group 2;\n");
        } else {
            asm volatile("cp.async.wait_group 0;\n");
        }
        __syncthreads();   // single barrier per ktile; stage distances safe mod 4

        const int cur = kt % STAGES;
        const uint32_t as_base = As_u + (uint32_t)(cur * A_STAGE) * 2;
        const uint32_t bs_base = Bs_u + (uint32_t)(cur * B_STAGE) * 2;

#pragma unroll
        for (int kk = 0; kk < BK; kk += 16) {
            uint32_t a[4][4];
            uint32_t b[4][4];   // [q][4]: nf=2q -> b[q]+0, nf=2q+1 -> b[q]+2
#pragma unroll
            for (int mf = 0; mf < 4; mf++) {
                uint32_t addr = as_base +
                    ((uint32_t)(a_row + mf * 16) * AST + kk + a_k8) * 2;
                ldmA(a[mf], addr);
            }
#pragma unroll
            for (int q = 0; q < 4; q++) {
                uint32_t addr = bs_base +
                    ((uint32_t)(kk + b_row) * BST + b_col + q * 16) * 2;
                ldmB4(b[q], addr);
            }
#pragma unroll
            for (int mf = 0; mf < 4; mf++)
#pragma unroll
                for (int nf = 0; nf < 8; nf++)
                    mma_f16(acc[mf][nf], a[mf], &b[nf >> 1][(nf & 1) * 2]);
        }
    }

#pragma unroll
    for (int mf = 0; mf < 4; mf++) {
        int r0 = bm + warpM * 64 + mf * 16 + (lane >> 2);
#pragma unroll
        for (int nf = 0; nf < 8; nf++) {
            int c0 = bn + warpN * 64 + nf * 8 + (lane & 3) * 2;
            *reinterpret_cast<float2*>(C + (size_t)r0 * N + c0) =
                make_float2(acc[mf][nf][0], acc[mf][nf][1]);
            *reinterpret_cast<float2*>(C + (size_t)(r0 + 8) * N + c0) =
                make_float2(acc[mf][nf][2], acc[mf][nf][3]);
        }
    }
}

// ---------------------------------------------------------------------------
// Launch (ordered so the profiler's fixed launch index hits the fused GEMM)
// ---------------------------------------------------------------------------
extern "C" void kernel_launch(void* const* d_in, const int* in_sizes, int n_in,
                              void* d_out, int out_size) {
    const float* x  = (const float*)d_in[0];
    const int*   gq = (const int*)d_in[1];
    const int*   gz = (const int*)d_in[2];
    const float* gs = (const float*)d_in[3];
    const int*   uq = (const int*)d_in[4];
    const int*   uz = (const int*)d_in[5];
    const float* us = (const float*)d_in[6];
    const int*   dq = (const int*)d_in[7];
    const int*   dz = (const int*)d_in[8];
    const float* ds = (const float*)d_in[9];
    float* out = (float*)d_out;

    __half *wg, *wu, *wd, *xh, *hh;
    cudaGetSymbolAddress((void**)&wg, g_wg);
    cudaGetSymbolAddress((void**)&wu, g_wu);
    cudaGetSymbolAddress((void**)&wd, g_wd);
    cudaGetSymbolAddress((void**)&xh, g_xh);
    cudaGetSymbolAddress((void**)&hh, g_h);

    cudaFuncSetAttribute(fused_gateup_kernel,
                         cudaFuncAttributeMaxDynamicSharedMemorySize, (int)FSMEM_BYTES);
    cudaFuncSetAttribute(gemm_f16_kernel,
                         cudaFuncAttributeMaxDynamicSharedMemorySize, (int)SMEM_BYTES);

    // 1) x to fp16
    x_to_half_kernel<<<(TOKENS * HIDDEN / 8 + 255) / 256, 256>>>(x, xh, TOKENS * HIDDEN / 8);

    // 2) dequant gate / up
    dequant_kernel<<<dim3(INTER / 256, HIDDEN / 8), 256>>>(gq, gz, gs, wg, HIDDEN, INTER);
    dequant_kernel<<<dim3(INTER / 256, HIDDEN / 8), 256>>>(uq, uz, us, wu, HIDDEN, INTER);

    // 3) fused gate+up -> h (fp16)   [launch #4 -> profiled]
    fused_gateup_kernel<<<dim3(INTER / FBN, TOKENS / FBM), 256, FSMEM_BYTES>>>(
        xh, wg, wu, hh, TOKENS, INTER, HIDDEN);

    // 4) dequant down
    dequant_kernel<<<dim3(HIDDEN / 256, INTER / 8), 256>>>(dq, dz, ds, wd, INTER, HIDDEN);

    // 5) down projection -> out (fp32)
    gemm_f16_kernel<<<dim3(HIDDEN / BN, TOKENS / BM), 256, SMEM_BYTES>>>(
        hh, wd, out, TOKENS, HIDDEN, INTER);
}

// round 14
// speedup vs baseline: 1.6818x; 1.6818x over previous
#include <cuda_runtime.h>
#include <cuda_fp16.h>
#include <cstdint>
#include <cstddef>

// Problem dims (fixed by the dataset)
#define TOKENS 8192
#define HIDDEN 2048
#define INTER  5632

// ---------------------------------------------------------------------------
// Scratch (device globals; no allocation allowed in kernel_launch)
// ---------------------------------------------------------------------------
__device__ __half g_wg[(size_t)HIDDEN * INTER];   // gate weight [H, I] fp16
__device__ __half g_wu[(size_t)HIDDEN * INTER];   // up weight   [H, I] fp16
__device__ __half g_wd[(size_t)INTER * HIDDEN];   // down weight [I, H] fp16
__device__ __half g_xh[(size_t)TOKENS * HIDDEN];  // x in fp16
__device__ __half g_h [(size_t)TOKENS * INTER];   // silu(xWg)*(xWu) in fp16

// ---------------------------------------------------------------------------
// Helpers
// ---------------------------------------------------------------------------
__device__ __forceinline__ void cp_async16(void* smem_dst, const void* gsrc) {
    uint32_t s = (uint32_t)__cvta_generic_to_shared(smem_dst);
    asm volatile("cp.async.cg.shared.global [%0], [%1], 16;\n" :: "r"(s), "l"(gsrc));
}
__device__ __forceinline__ void cp_commit() {
    asm volatile("cp.async.commit_group;\n");
}

__device__ __forceinline__ void ldmA(uint32_t r[4], uint32_t addr) {
    asm volatile("ldmatrix.sync.aligned.m8n8.x4.shared.b16 {%0,%1,%2,%3}, [%4];"
                 : "=r"(r[0]), "=r"(r[1]), "=r"(r[2]), "=r"(r[3]) : "r"(addr));
}
// x4 trans: returns {k0-7/n0-7, k8-15/n0-7, k0-7/n8-15, k8-15/n8-15}
__device__ __forceinline__ void ldmB4(uint32_t r[4], uint32_t addr) {
    asm volatile("ldmatrix.sync.aligned.m8n8.x4.trans.shared.b16 {%0,%1,%2,%3}, [%4];"
                 : "=r"(r[0]), "=r"(r[1]), "=r"(r[2]), "=r"(r[3]) : "r"(addr));
}

__device__ __forceinline__ void mma_f16(float c[4], const uint32_t a[4], const uint32_t* b) {
    asm volatile(
        "mma.sync.aligned.m16n8k16.row.col.f32.f16.f16.f32 "
        "{%0,%1,%2,%3}, {%4,%5,%6,%7}, {%8,%9}, {%0,%1,%2,%3};\n"
        : "+f"(c[0]), "+f"(c[1]), "+f"(c[2]), "+f"(c[3])
        : "r"(a[0]), "r"(a[1]), "r"(a[2]), "r"(a[3]),
          "r"(b[0]), "r"(b[1]));
}

__device__ __forceinline__ float silu(float v) {
    return v / (1.0f + __expf(-v));
}

// ---------------------------------------------------------------------------
// GPTQ int4 dequant -> fp16 [K, N] row-major
// ---------------------------------------------------------------------------
__global__ void dequant_kernel(const int* __restrict__ qw,
                               const int* __restrict__ qz,
                               const float* __restrict__ sc,
                               __half* __restrict__ w,
                               int in_dim, int out) {
    int o = blockIdx.x * blockDim.x + threadIdx.x;
    int kp = blockIdx.y;
    if (o >= out) return;
    int grp = kp >> 4;
    unsigned q = (unsigned)qw[(size_t)kp * out + o];
    unsigned zw = (unsigned)qz[(size_t)grp * (out >> 3) + (o >> 3)];
    int z = (int)((zw >> ((o & 7) * 4)) & 0xF) + 1;
    float s = sc[(size_t)grp * out + o];
#pragma unroll
    for (int j = 0; j < 8; j++) {
        int qv = (int)((q >> (4 * j)) & 0xF);
        w[(size_t)(kp * 8 + j) * out + o] = __float2half_rn((float)(qv - z) * s);
    }
}

// Convert x to fp16 (8 floats / thread)
__global__ void x_to_half_kernel(const float* __restrict__ x, __half* __restrict__ y, int n8) {
    int i = blockIdx.x * blockDim.x + threadIdx.x;
    if (i >= n8) return;
    float4 v0 = reinterpret_cast<const float4*>(x)[2 * i];
    float4 v1 = reinterpret_cast<const float4*>(x)[2 * i + 1];
    __half2 h[4];
    h[0] = __floats2half2_rn(v0.x, v0.y);
    h[1] = __floats2half2_rn(v0.z, v0.w);
    h[2] = __floats2half2_rn(v1.x, v1.y);
    h[3] = __floats2half2_rn(v1.z, v1.w);
    reinterpret_cast<uint4*>(y)[i] = *reinterpret_cast<uint4*>(h);
}

// ---------------------------------------------------------------------------
// Fused gate+up GEMM: h = fp16( silu(A@Bg) * (A@Bu) ), A[M,K], B*[K,N]
// CTA tile 64x128, BK=32, 4 stages, 128 threads = 4 warps 1(M)x4(N),
// warp tile 64x32 per matrix. R7 pipeline (dist-3 prefetch, wait_group 3,
// two __syncthreads). 2 CTAs per SM (90KB smem, ~180 regs).
// ---------------------------------------------------------------------------
constexpr int FBM = 64, FBN = 128, FBK = 32, FSTAGES = 4;
constexpr int FAST = 40;                 // halves per A row
constexpr int FBST = 136;                // halves per B row (272B)
constexpr int FA_STAGE = FBM * FAST;     // 2560 halves
constexpr int FB_STAGE = FBK * FBST;     // 4352 halves
constexpr size_t FSMEM_BYTES = (size_t)FSTAGES * (FA_STAGE + 2 * FB_STAGE) * 2; // 90,112

__global__ void __launch_bounds__(128, 2)
fused_gateup_kernel(const __half* __restrict__ A,
                    const __half* __restrict__ Bg,
                    const __half* __restrict__ Bu,
                    __half* __restrict__ H, int M, int N, int K) {
    extern __shared__ __half smem[];
    __half* As  = smem;
    __half* Bgs = smem + FSTAGES * FA_STAGE;
    __half* Bus = Bgs + FSTAGES * FB_STAGE;
    const uint32_t As_u  = (uint32_t)__cvta_generic_to_shared(As);
    const uint32_t Bgs_u = (uint32_t)__cvta_generic_to_shared(Bgs);
    const uint32_t Bus_u = (uint32_t)__cvta_generic_to_shared(Bus);

    const int tid  = threadIdx.x;
    const int lane = tid & 31;
    const int wid  = tid >> 5;      // 0..3
    const int warpN = wid;          // 1(M) x 4(N)
    const int bm = blockIdx.y * FBM;
    const int bn = blockIdx.x * FBN;

    // cp.async mapping (16B chunks), 128 threads:
    // A: 64 rows x 4 chunks = 256 -> 2/thread. B each: 32 rows x 16 chunks = 512 -> 4/thread.
    const int af8 = tid & 3;       // chunk in A row
    const int ar0 = tid >> 2;      // 0..31, rows +{0,32}
    const int bf8 = tid & 15;      // chunk in B row
    const int br0 = tid >> 4;      // 0..7, rows +{0,8,16,24}

    auto load_stage = [&](int st, int k0) {
        __half* as = As + st * FA_STAGE;
        __half* bgs = Bgs + st * FB_STAGE;
        __half* bus = Bus + st * FB_STAGE;
#pragma unroll
        for (int i = 0; i < 2; i++) {
            int r = ar0 + i * 32;
            cp_async16(as + r * FAST + af8 * 8,
                       A + (size_t)(bm + r) * K + k0 + af8 * 8);
        }
#pragma unroll
        for (int i = 0; i < 4; i++) {
            int r = br0 + i * 8;
            cp_async16(bgs + r * FBST + bf8 * 8,
                       Bg + (size_t)(k0 + r) * N + bn + bf8 * 8);
            cp_async16(bus + r * FBST + bf8 * 8,
                       Bu + (size_t)(k0 + r) * N + bn + bf8 * 8);
        }
        cp_commit();
    };

    float accg[4][4][4], accu[4][4][4];
#pragma unroll
    for (int mf = 0; mf < 4; mf++)
#pragma unroll
        for (int nf = 0; nf < 4; nf++)
#pragma unroll
            for (int i = 0; i < 4; i++) { accg[mf][nf][i] = 0.0f; accu[mf][nf][i] = 0.0f; }

    const int kTiles = K / FBK;
    load_stage(0, 0);
    load_stage(1, FBK);
    load_stage(2, 2 * FBK);

    // Fragment addressing
    const int a_row = lane & 15;                               // + mf*16 covers 64 rows
    const int a_k8  = (lane >> 4) * 8;
    const int b_row = (lane & 7) | (((lane >> 3) & 1) << 3);   // k offset 0..15
    const int b_col = warpN * 32 + ((lane >> 4) & 1) * 8;      // + q*16

    for (int kt = 0; kt < kTiles; ++kt) {
        if (kt + 3 < kTiles) {
            load_stage((kt + 3) % FSTAGES, (kt + 3) * FBK);
            asm volatile("cp.async.wait_group 3;\n");
        } else {
            asm volatile("cp.async.wait_group 0;\n");
        }
        __syncthreads();

        const int cur = kt % FSTAGES;
        const uint32_t as_base = As_u + (uint32_t)(cur * FA_STAGE) * 2;
        const uint32_t bg_base = Bgs_u + (uint32_t)(cur * FB_STAGE) * 2;
        const uint32_t bu_base = Bus_u + (uint32_t)(cur * FB_STAGE) * 2;

#pragma unroll
        for (int kk = 0; kk < FBK; kk += 16) {
            uint32_t a[4][4];
            uint32_t bg[2][4];
            uint32_t bu[2][4];
#pragma unroll
            for (int mf = 0; mf < 4; mf++) {
                uint32_t addr = as_base +
                    ((uint32_t)(a_row + mf * 16) * FAST + kk + a_k8) * 2;
                ldmA(a[mf], addr);
            }
#pragma unroll
            for (int q = 0; q < 2; q++) {
                uint32_t off = ((uint32_t)(kk + b_row) * FBST + b_col + q * 16) * 2;
                ldmB4(bg[q], bg_base + off);
                ldmB4(bu[q], bu_base + off);
            }
#pragma unroll
            for (int mf = 0; mf < 4; mf++)
#pragma unroll
                for (int nf = 0; nf < 4; nf++) {
                    mma_f16(accg[mf][nf], a[mf], &bg[nf >> 1][(nf & 1) * 2]);
                    mma_f16(accu[mf][nf], a[mf], &bu[nf >> 1][(nf & 1) * 2]);
                }
        }
        __syncthreads();   // protect stage slots before the next prefetch
    }

    // Epilogue: h = fp16(silu(g)*u)
#pragma unroll
    for (int mf = 0; mf < 4; mf++) {
        int r0 = bm + mf * 16 + (lane >> 2);
#pragma unroll
        for (int nf = 0; nf < 4; nf++) {
            int c0 = bn + warpN * 32 + nf * 8 + (lane & 3) * 2;
            float* g = accg[mf][nf];
            float* u = accu[mf][nf];
            *reinterpret_cast<__half2*>(H + (size_t)r0 * N + c0) =
                __floats2half2_rn(silu(g[0]) * u[0], silu(g[1]) * u[1]);
            *reinterpret_cast<__half2*>(H + (size_t)(r0 + 8) * N + c0) =
                __floats2half2_rn(silu(g[2]) * u[2], silu(g[3]) * u[3]);
        }
    }
}

// ---------------------------------------------------------------------------
// fp16 GEMM (down proj): C[M,N] = A[M,K] @ B[K,N], fp32 out
// CTA tile 128x128, BK=32, 4 stages, 128 threads = 4 warps 2(M)x2(N),
// warp tile 64x64. R7 pipeline. 2 CTAs per SM (76KB smem, ~210 regs).
// ---------------------------------------------------------------------------
constexpr int BM = 128, BN = 128, BK = 32, STAGES = 4;
constexpr int AST = 40;               // halves per A row
constexpr int BST = 136;              // halves per B row
constexpr int A_STAGE = BM * AST;     // 5120 halves
constexpr int B_STAGE = BK * BST;     // 4352 halves
constexpr size_t SMEM_BYTES = (size_t)STAGES * (A_STAGE + B_STAGE) * 2;  // 75,776

__global__ void __launch_bounds__(128, 2)
gemm_f16_kernel(const __half* __restrict__ A, const __half* __restrict__ B,
                float* __restrict__ C, int M, int N, int K) {
    extern __shared__ __half smem[];
    __half* As = smem;
    __half* Bs = smem + STAGES * A_STAGE;
    const uint32_t As_u = (uint32_t)__cvta_generic_to_shared(As);
    const uint32_t Bs_u = (uint32_t)__cvta_generic_to_shared(Bs);

    const int tid  = threadIdx.x;
    const int lane = tid & 31;
    const int wid  = tid >> 5;      // 0..3
    const int warpM = wid & 1;      // 0..1
    const int warpN = wid >> 1;     // 0..1
    const int bm = blockIdx.y * BM;
    const int bn = blockIdx.x * BN;

    // cp.async mapping, 128 threads:
    // A: 128 rows x 4 chunks = 512 -> 4/thread. B: 32 rows x 16 chunks = 512 -> 4/thread.
    const int af8 = tid & 3;
    const int ar0 = tid >> 2;      // 0..31, rows +{0,32,64,96}
    const int bf8 = tid & 15;
    const int br0 = tid >> 4;      // 0..7, rows +{0,8,16,24}

    auto load_stage = [&](int st, int k0) {
        __half* as = As + st * A_STAGE;
        __half* bs = Bs + st * B_STAGE;
#pragma unroll
        for (int i = 0; i < 4; i++) {
            int r = ar0 + i * 32;
            cp_async16(as + r * AST + af8 * 8,
                       A + (size_t)(bm + r) * K + k0 + af8 * 8);
        }
#pragma unroll
        for (int i = 0; i < 4; i++) {
            int r = br0 + i * 8;
            cp_async16(bs + r * BST + bf8 * 8,
                       B + (size_t)(k0 + r) * N + bn + bf8 * 8);
        }
        cp_commit();
    };

    float acc[4][8][4];
#pragma unroll
    for (int mf = 0; mf < 4; mf++)
#pragma unroll
        for (int nf = 0; nf < 8; nf++)
#pragma unroll
            for (int i = 0; i < 4; i++) acc[mf][nf][i] = 0.0f;

    const int kTiles = K / BK;
    load_stage(0, 0);
    load_stage(1, BK);
    load_stage(2, 2 * BK);

    const int a_row = warpM * 64 + (lane & 15);
    const int a_k8  = (lane >> 4) * 8;
    const int b_row = (lane & 7) | (((lane >> 3) & 1) << 3);
    const int b_col = warpN * 64 + ((lane >> 4) & 1) * 8;   // + q*16

    for (int kt = 0; kt < kTiles; ++kt) {
        if (kt + 3 < kTiles) {
            load_stage((kt + 3) % STAGES, (kt + 3) * BK);
            asm volatile("cp.async.wait_group 3;\n");
        } else {
            asm volatile("cp.async.wait_group 0;\n");
        }
        __syncthreads();

        const int cur = kt % STAGES;
        const uint32_t as_base = As_u + (uint32_t)(cur * A_STAGE) * 2;
        const uint32_t bs_base = Bs_u + (uint32_t)(cur * B_STAGE) * 2;

#pragma unroll
        for (int kk = 0; kk < BK; kk += 16) {
            uint32_t a[4][4];
            uint32_t b[4][4];   // [q][4]: nf=2q -> b[q]+0, nf=2q+1 -> b[q]+2
#pragma unroll
            for (int mf = 0; mf < 4; mf++) {
                uint32_t addr = as_base +
                    ((uint32_t)(a_row + mf * 16) * AST + kk + a_k8) * 2;
                ldmA(a[mf], addr);
            }
#pragma unroll
            for (int q = 0; q < 4; q++) {
                uint32_t addr = bs_base +
                    ((uint32_t)(kk + b_row) * BST + b_col + q * 16) * 2;
                ldmB4(b[q], addr);
            }
#pragma unroll
            for (int mf = 0; mf < 4; mf++)
#pragma unroll
                for (int nf = 0; nf < 8; nf++)
                    mma_f16(acc[mf][nf], a[mf], &b[nf >> 1][(nf & 1) * 2]);
        }
        __syncthreads();   // protect stage slots before the next prefetch
    }

#pragma unroll
    for (int mf = 0; mf < 4; mf++) {
        int r0 = bm + warpM * 64 + mf * 16 + (lane >> 2);
#pragma unroll
        for (int nf = 0; nf < 8; nf++) {
            int c0 = bn + warpN * 64 + nf * 8 + (lane & 3) * 2;
            *reinterpret_cast<float2*>(C + (size_t)r0 * N + c0) =
                make_float2(acc[mf][nf][0], acc[mf][nf][1]);
            *reinterpret_cast<float2*>(C + (size_t)(r0 + 8) * N + c0) =
                make_float2(acc[mf][nf][2], acc[mf][nf][3]);
        }
    }
}

// ---------------------------------------------------------------------------
// Launch (ordered so the profiler's fixed launch index hits the fused GEMM)
// ---------------------------------------------------------------------------
extern "C" void kernel_launch(void* const* d_in, const int* in_sizes, int n_in,
                              void* d_out, int out_size) {
    const float* x  = (const float*)d_in[0];
    const int*   gq = (const int*)d_in[1];
    const int*   gz = (const int*)d_in[2];
    const float* gs = (const float*)d_in[3];
    const int*   uq = (const int*)d_in[4];
    const int*   uz = (const int*)d_in[5];
    const float* us = (const float*)d_in[6];
    const int*   dq = (const int*)d_in[7];
    const int*   dz = (const int*)d_in[8];
    const float* ds = (const float*)d_in[9];
    float* out = (float*)d_out;

    __half *wg, *wu, *wd, *xh, *hh;
    cudaGetSymbolAddress((void**)&wg, g_wg);
    cudaGetSymbolAddress((void**)&wu, g_wu);
    cudaGetSymbolAddress((void**)&wd, g_wd);
    cudaGetSymbolAddress((void**)&xh, g_xh);
    cudaGetSymbolAddress((void**)&hh, g_h);

    cudaFuncSetAttribute(fused_gateup_kernel,
                         cudaFuncAttributeMaxDynamicSharedMemorySize, (int)FSMEM_BYTES);
    cudaFuncSetAttribute(gemm_f16_kernel,
                         cudaFuncAttributeMaxDynamicSharedMemorySize, (int)SMEM_BYTES);

    // 1) x to fp16
    x_to_half_kernel<<<(TOKENS * HIDDEN / 8 + 255) / 256, 256>>>(x, xh, TOKENS * HIDDEN / 8);

    // 2) dequant gate / up
    dequant_kernel<<<dim3(INTER / 256, HIDDEN / 8), 256>>>(gq, gz, gs, wg, HIDDEN, INTER);
    dequant_kernel<<<dim3(INTER / 256, HIDDEN / 8), 256>>>(uq, uz, us, wu, HIDDEN, INTER);

    // 3) fused gate+up -> h (fp16)   [launch #4 -> profiled]
    fused_gateup_kernel<<<dim3(INTER / FBN, TOKENS / FBM), 128, FSMEM_BYTES>>>(
        xh, wg, wu, hh, TOKENS, INTER, HIDDEN);

    // 4) dequant down
    dequant_kernel<<<dim3(HIDDEN / 256, INTER / 8), 256>>>(dq, dz, ds, wd, INTER, HIDDEN);

    // 5) down projection -> out (fp32)
    gemm_f16_kernel<<<dim3(HIDDEN / BN, TOKENS / BM), 128, SMEM_BYTES>>>(
        hh, wd, out, TOKENS, HIDDEN, INTER);
}